// round 2
// baseline (speedup 1.0000x reference)
#include <cuda_runtime.h>
#include <cuda_bf16.h>
#include <math.h>

// ---------------------------------------------------------------------------
// Problem constants (shapes are fixed by the dataset)
// ---------------------------------------------------------------------------
#define NN    50000
#define EE    800000
#define EMB   256
#define HID   512
#define DDISC 64
#define DCONT 13
#define CAT   (4*EMB)      // 1024
#define SLOPE 0.01f

// ---------------------------------------------------------------------------
// Scratch (no cudaMalloc allowed) — __device__ globals
// ---------------------------------------------------------------------------
__device__ float g_X4[(long)NN*CAT];     // concat(x_d, x_c1, x_c2, x_g)
__device__ float g_G0[(long)NN*EMB];     // gcn input / ping
__device__ float g_G1[(long)NN*EMB];     // pong
__device__ float g_Y [(long)NN*EMB];     // x @ Wg (pre-aggregation)
__device__ float g_H [(long)NN*HID];     // h_ci
__device__ float g_S [(long)NN*EMB];     // s (HID/2 = 256)
__device__ float g_sci[NN];
__device__ float g_dinv[NN];
__device__ int   g_cnt[NN];
__device__ int   g_rowptr[NN+1];
__device__ int   g_cursor[NN];
__device__ int   g_colsrc[EE];
__device__ int   g_is64;                 // edge_index dtype flag (1 = int64)

// ---------------------------------------------------------------------------
// Edge dtype probe: view buffer as int32; for int64 data with values < 2^31,
// every odd 32-bit word is 0. For int32 data, odd words are random node ids.
// ---------------------------------------------------------------------------
__global__ void probe_kernel(const int* __restrict__ ei32, int nwords)
{
    __shared__ int nz;
    if (threadIdx.x == 0) nz = 0;
    __syncthreads();
    int lim = nwords < 4096 ? nwords : 4096;
    for (int i = 1 + 2 * threadIdx.x; i < lim; i += 2 * blockDim.x)
        if (ei32[i] != 0) atomicAdd(&nz, 1);
    __syncthreads();
    if (threadIdx.x == 0) g_is64 = (nz == 0) ? 1 : 0;
}

__device__ __forceinline__ int edge_at(const void* base, long i, int is64)
{
    return is64 ? (int)((const long long*)base)[i] : ((const int*)base)[i];
}

// ---------------------------------------------------------------------------
// Tiled fp32 SGEMM:  C[M,NC] = act(A[M,K] @ W[K,NC] + bias)
// Block tile 128x128, BK=8, 256 threads, 8x8 per thread.
// ACT: 0 = none, 1 = leaky_relu
// ---------------------------------------------------------------------------
template<int ACT>
__global__ __launch_bounds__(256)
void sgemm_kernel(const float* __restrict__ A, int lda,
                  const float* __restrict__ W,
                  const float* __restrict__ bias,
                  float* __restrict__ C, int ldc,
                  int M, int K, int NC)
{
    const int BM = 128, BN = 128, BK = 8;
    __shared__ float As[BK][BM];
    __shared__ float Ws[BK][BN];

    int tid = threadIdx.x;
    int tx = tid & 15;          // 0..15 -> output cols
    int ty = tid >> 4;          // 0..15 -> output rows
    int row0 = blockIdx.y * BM;
    int col0 = blockIdx.x * BN;

    float acc[8][8];
    #pragma unroll
    for (int i = 0; i < 8; i++)
        #pragma unroll
        for (int j = 0; j < 8; j++) acc[i][j] = 0.f;

    int a_row = tid >> 1;             // 0..127
    int a_col = (tid & 1) * 4;        // 0 or 4
    int w_k = tid >> 5;               // 0..7
    int w_n = (tid & 31) * 4;         // 0..124

    for (int k0 = 0; k0 < K; k0 += BK) {
        #pragma unroll
        for (int j = 0; j < 4; j++) {
            int r = row0 + a_row, c = k0 + a_col + j;
            As[a_col + j][a_row] = (r < M && c < K) ? A[(long)r * lda + c] : 0.f;
        }
        #pragma unroll
        for (int j = 0; j < 4; j++) {
            int kk = k0 + w_k, nn = col0 + w_n + j;
            Ws[w_k][w_n + j] = (kk < K && nn < NC) ? W[(long)kk * NC + nn] : 0.f;
        }
        __syncthreads();
        #pragma unroll
        for (int k = 0; k < BK; k++) {
            float a[8], b[8];
            #pragma unroll
            for (int i = 0; i < 8; i++) a[i] = As[k][ty * 8 + i];
            #pragma unroll
            for (int j = 0; j < 8; j++) b[j] = Ws[k][tx * 8 + j];
            #pragma unroll
            for (int i = 0; i < 8; i++)
                #pragma unroll
                for (int j = 0; j < 8; j++)
                    acc[i][j] += a[i] * b[j];
        }
        __syncthreads();
    }

    #pragma unroll
    for (int i = 0; i < 8; i++) {
        int r = row0 + ty * 8 + i;
        if (r >= M) continue;
        #pragma unroll
        for (int j = 0; j < 8; j++) {
            int c = col0 + tx * 8 + j;
            if (c >= NC) continue;
            float v = acc[i][j];
            if (bias) v += bias[c];
            if (ACT == 1) v = v > 0.f ? v : SLOPE * v;
            C[(long)r * ldc + c] = v;
        }
    }
}

// ---------------------------------------------------------------------------
// Graph preprocessing
// ---------------------------------------------------------------------------
__global__ void zero_cnt_kernel(int n) {
    int i = blockIdx.x * blockDim.x + threadIdx.x;
    if (i < n) g_cnt[i] = 0;
}

__global__ void count_kernel(const void* __restrict__ ei, int e, int n) {
    int i = blockIdx.x * blockDim.x + threadIdx.x;
    if (i >= e) return;
    int is64 = g_is64;
    int d = edge_at(ei, (long)e + i, is64);
    if ((unsigned)d < (unsigned)n) atomicAdd(&g_cnt[d], 1);
}

__global__ void dinv_kernel(int n) {
    int i = blockIdx.x * blockDim.x + threadIdx.x;
    if (i < n) g_dinv[i] = rsqrtf((float)(g_cnt[i] + 1));  // +1 self loop
}

// single-block exclusive scan of g_cnt -> g_rowptr (and g_cursor copy)
__global__ void scan_kernel(int n) {
    __shared__ int sh[1024];
    __shared__ int carry_sh;
    int tid = threadIdx.x;
    if (tid == 0) carry_sh = 0;
    __syncthreads();
    for (int base = 0; base < n; base += 1024) {
        int v = (base + tid < n) ? g_cnt[base + tid] : 0;
        sh[tid] = v;
        __syncthreads();
        for (int off = 1; off < 1024; off <<= 1) {
            int t = (tid >= off) ? sh[tid - off] : 0;
            __syncthreads();
            sh[tid] += t;
            __syncthreads();
        }
        int carry = carry_sh;
        if (base + tid < n) {
            int ex = carry + sh[tid] - v;
            g_rowptr[base + tid] = ex;
            g_cursor[base + tid] = ex;
        }
        __syncthreads();
        if (tid == 0) carry_sh = carry + sh[1023];
        __syncthreads();
    }
    if (threadIdx.x == 0) g_rowptr[n] = carry_sh;
}

__global__ void fill_kernel(const void* __restrict__ ei, int e, int n) {
    int i = blockIdx.x * blockDim.x + threadIdx.x;
    if (i >= e) return;
    int is64 = g_is64;
    int s = edge_at(ei, i, is64);
    int d = edge_at(ei, (long)e + i, is64);
    if ((unsigned)d < (unsigned)n && (unsigned)s < (unsigned)n) {
        int pos = atomicAdd(&g_cursor[d], 1);
        if (pos < EE) g_colsrc[pos] = s;
    }
}

// ---------------------------------------------------------------------------
// GCN aggregation: out[i] = lrelu( dinv[i]*sum_{src->i} Y[src]*dinv[src]
//                                  + dinv[i]^2 * Y[i] + bias )
// one warp per node; 256 cols = 8 floats per lane.
// ---------------------------------------------------------------------------
__global__ __launch_bounds__(256)
void agg_kernel(const float* __restrict__ Y, const float* __restrict__ bias,
                float* __restrict__ out, int ldc, int n)
{
    int warp = (blockIdx.x * blockDim.x + threadIdx.x) >> 5;
    int lane = threadIdx.x & 31;
    if (warp >= n) return;
    int beg = g_rowptr[warp], end = g_rowptr[warp + 1];
    float acc[8];
    #pragma unroll
    for (int j = 0; j < 8; j++) acc[j] = 0.f;
    for (int e = beg; e < end; e++) {
        int s = g_colsrc[e];
        float w = g_dinv[s];
        const float* yr = Y + (long)s * EMB;
        #pragma unroll
        for (int j = 0; j < 8; j++)
            acc[j] += yr[lane + 32 * j] * w;
    }
    float di = g_dinv[warp];
    const float* ys = Y + (long)warp * EMB;
    #pragma unroll
    for (int j = 0; j < 8; j++) {
        int c = lane + 32 * j;
        float v = di * acc[j] + di * di * ys[c] + bias[c];
        v = v > 0.f ? v : SLOPE * v;
        out[(long)warp * ldc + c] = v;
    }
}

// ---------------------------------------------------------------------------
// Final: s_ci = sigmoid(S @ Wl2 + bl2), one warp per node (K=256)
// ---------------------------------------------------------------------------
__global__ __launch_bounds__(256)
void final_kernel(const float* __restrict__ Wl2, const float* __restrict__ bl2, int n)
{
    int warp = (blockIdx.x * blockDim.x + threadIdx.x) >> 5;
    int lane = threadIdx.x & 31;
    if (warp >= n) return;
    const float* sr = g_S + (long)warp * EMB;
    float a = 0.f;
    #pragma unroll
    for (int j = 0; j < 8; j++) {
        int c = lane + 32 * j;
        a += sr[c] * Wl2[c];
    }
    #pragma unroll
    for (int off = 16; off > 0; off >>= 1)
        a += __shfl_xor_sync(0xffffffffu, a, off);
    if (lane == 0)
        g_sci[warp] = 1.f / (1.f + expf(-(a + bl2[0])));
}

// ---------------------------------------------------------------------------
// Output assembly: (s_ci, s_ci, s_ci, h_ci, h_ci) flattened
// ---------------------------------------------------------------------------
__global__ void writeout_kernel(float* __restrict__ out, int n)
{
    long idx = (long)blockIdx.x * blockDim.x + threadIdx.x;
    long tot = (long)n * HID;
    if (idx < tot) {
        float v = g_H[idx];
        out[3L * n + idx] = v;
        out[3L * n + tot + idx] = v;
    }
    if (idx < n) {
        float v = g_sci[idx];
        out[idx] = v;
        out[(long)n + idx] = v;
        out[2L * n + idx] = v;
    }
}

// ---------------------------------------------------------------------------
// Launch
// ---------------------------------------------------------------------------
extern "C" void kernel_launch(void* const* d_in, const int* in_sizes, int n_in,
                              void* d_out, int out_size)
{
    const float* discrete_x = (const float*)d_in[0];
    const float* continous_x = (const float*)d_in[1];
    const float* Wd  = (const float*)d_in[2];
    const float* bd  = (const float*)d_in[3];
    const float* Wc1 = (const float*)d_in[4];
    const float* bc1 = (const float*)d_in[5];
    const float* Wc2 = (const float*)d_in[6];
    const float* bc2 = (const float*)d_in[7];
    const float* Wg0 = (const float*)d_in[8];
    const float* bg0 = (const float*)d_in[9];
    const float* Wg1 = (const float*)d_in[10];
    const float* bg1 = (const float*)d_in[11];
    const float* Wg2 = (const float*)d_in[12];
    const float* bg2 = (const float*)d_in[13];
    const float* Wf  = (const float*)d_in[14];
    const float* bf  = (const float*)d_in[15];
    const float* Wl1 = (const float*)d_in[16];
    const float* bl1 = (const float*)d_in[17];
    const float* Wl2 = (const float*)d_in[18];
    const float* bl2 = (const float*)d_in[19];
    const void*  edge_index = d_in[20];

    const int n = in_sizes[0] / DDISC;       // 50000
    const int e = in_sizes[20] / 2;          // 800000 (element count same for i32/i64)

    float *pX4, *pG0, *pG1, *pY, *pH, *pS;
    cudaGetSymbolAddress((void**)&pX4, g_X4);
    cudaGetSymbolAddress((void**)&pG0, g_G0);
    cudaGetSymbolAddress((void**)&pG1, g_G1);
    cudaGetSymbolAddress((void**)&pY,  g_Y);
    cudaGetSymbolAddress((void**)&pH,  g_H);
    cudaGetSymbolAddress((void**)&pS,  g_S);

    dim3 blk(256);

    // ---- edge dtype probe + graph preprocessing (CSR by dst + dinv) ----
    probe_kernel<<<1, 256>>>((const int*)edge_index, 2 * e);
    zero_cnt_kernel<<<(n + 255) / 256, blk>>>(n);
    count_kernel<<<(e + 255) / 256, blk>>>(edge_index, e, n);
    dinv_kernel<<<(n + 255) / 256, blk>>>(n);
    scan_kernel<<<1, 1024>>>(n);
    fill_kernel<<<(e + 255) / 256, blk>>>(edge_index, e, n);

    // ---- feature embeddings into the concat buffer X4 ----
    {
        dim3 grid((EMB + 127) / 128, (n + 127) / 128);
        sgemm_kernel<1><<<grid, blk>>>(discrete_x, DDISC, Wd, bd, pX4 + 0,    CAT, n, DDISC, EMB);
        sgemm_kernel<1><<<grid, blk>>>(continous_x,         3*DCONT, Wc1, bc1, pX4 + EMB,   CAT, n, DCONT, EMB);
        sgemm_kernel<1><<<grid, blk>>>(continous_x + DCONT, 3*DCONT, Wc2, bc2, pX4 + 2*EMB, CAT, n, DCONT, EMB);
        sgemm_kernel<1><<<grid, blk>>>(discrete_x, DDISC, Wg0, bg0, pG0, EMB, n, DDISC, EMB);
    }

    // ---- GCN conv 1: Y = G0 @ Wg1 ; aggregate -> G1 ----
    {
        dim3 grid((EMB + 127) / 128, (n + 127) / 128);
        sgemm_kernel<0><<<grid, blk>>>(pG0, EMB, Wg1, (const float*)nullptr, pY, EMB, n, EMB, EMB);
        agg_kernel<<<(n * 32 + 255) / 256, blk>>>(pY, bg1, pG1, EMB, n);
        // ---- GCN conv 2: Y = G1 @ Wg2 ; aggregate -> X4[:, 768:1024] ----
        sgemm_kernel<0><<<grid, blk>>>(pG1, EMB, Wg2, (const float*)nullptr, pY, EMB, n, EMB, EMB);
        agg_kernel<<<(n * 32 + 255) / 256, blk>>>(pY, bg2, pX4 + 3*EMB, CAT, n);
    }

    // ---- fusion MLP ----
    {
        dim3 gridH((HID + 127) / 128, (n + 127) / 128);
        sgemm_kernel<1><<<gridH, blk>>>(pX4, CAT, Wf, bf, pH, HID, n, CAT, HID);
        dim3 gridS((EMB + 127) / 128, (n + 127) / 128);
        sgemm_kernel<1><<<gridS, blk>>>(pH, HID, Wl1, bl1, pS, EMB, n, HID, EMB);
    }

    // ---- final sigmoid head ----
    final_kernel<<<(n * 32 + 255) / 256, blk>>>(Wl2, bl2, n);

    // ---- assemble output tuple ----
    {
        long tot = (long)n * HID;
        writeout_kernel<<<(unsigned)((tot + 255) / 256), blk>>>((float*)d_out, n);
    }
}

// round 4
// speedup vs baseline: 2.3865x; 2.3865x over previous
#include <cuda_runtime.h>
#include <cuda_bf16.h>
#include <math.h>
#include <stdint.h>

// ---------------------------------------------------------------------------
// Problem constants
// ---------------------------------------------------------------------------
#define NN    50000
#define EE    800000
#define EMB   256
#define HID   512
#define DDISC 64
#define DCONT 13
#define CAT   (4*EMB)      // 1024
#define SLOPE 0.01f

// ---------------------------------------------------------------------------
// Scratch — __device__ globals (no cudaMalloc allowed)
// ---------------------------------------------------------------------------
__device__ float g_X4[(long)NN*CAT];
__device__ float g_G0[(long)NN*EMB];
__device__ float g_G1[(long)NN*EMB];
__device__ float g_Y [(long)NN*EMB];
__device__ float g_H [(long)NN*HID];
__device__ float g_S [(long)NN*EMB];
__device__ float g_sci[NN];
__device__ float g_dinv[NN];
__device__ int   g_cnt[NN];
__device__ int   g_rowptr[NN+1];
__device__ int   g_cursor[NN];
__device__ int   g_colsrc[EE];
__device__ int   g_is64;

// bf16 split buffers (hi/lo)
__device__ __align__(16) __nv_bfloat16 g_Ah[(long)NN*CAT];   // X4 split
__device__ __align__(16) __nv_bfloat16 g_Al[(long)NN*CAT];
__device__ __align__(16) __nv_bfloat16 g_Gh[(long)NN*EMB];   // G / H splits (reused)
__device__ __align__(16) __nv_bfloat16 g_Gl[(long)NN*EMB];
__device__ __align__(16) __nv_bfloat16 g_Hh[(long)NN*HID];
__device__ __align__(16) __nv_bfloat16 g_Hl[(long)NN*HID];
__device__ __align__(16) __nv_bfloat16 g_Dh[(long)NN*DDISC]; // discrete_x split
__device__ __align__(16) __nv_bfloat16 g_Dl[(long)NN*DDISC];
__device__ __align__(16) __nv_bfloat16 g_Wth[(long)CAT*HID]; // transposed weight split (reused)
__device__ __align__(16) __nv_bfloat16 g_Wtl[(long)CAT*HID];

// ---------------------------------------------------------------------------
// mma.sync helpers (base ISA: works on compute_103 AND sm_103a)
// ---------------------------------------------------------------------------
__device__ __forceinline__ uint32_t smem_u32(const void* p) {
    uint32_t a;
    asm("{ .reg .u64 t; cvta.to.shared.u64 t, %1; cvt.u32.u64 %0, t; }" : "=r"(a) : "l"(p));
    return a;
}
__device__ __forceinline__ void ldsm4(uint32_t& r0, uint32_t& r1, uint32_t& r2, uint32_t& r3,
                                      uint32_t addr) {
    asm volatile("ldmatrix.sync.aligned.m8n8.x4.shared.b16 {%0,%1,%2,%3}, [%4];"
                 : "=r"(r0), "=r"(r1), "=r"(r2), "=r"(r3) : "r"(addr));
}
__device__ __forceinline__ void mma16816(float* c, const uint32_t* a, const uint32_t* b) {
    asm volatile(
        "mma.sync.aligned.m16n8k16.row.col.f32.bf16.bf16.f32 "
        "{%0,%1,%2,%3}, {%4,%5,%6,%7}, {%8,%9}, {%0,%1,%2,%3};"
        : "+f"(c[0]), "+f"(c[1]), "+f"(c[2]), "+f"(c[3])
        : "r"(a[0]), "r"(a[1]), "r"(a[2]), "r"(a[3]), "r"(b[0]), "r"(b[1]));
}
// byte offset inside a [rows][32 halfs] tile (row stride 64B, 16B-chunk swizzle)
__device__ __forceinline__ uint32_t swa(int r, int ci) {
    return (uint32_t)(r * 64 + ((ci ^ (r & 3) ^ ((r >> 2) & 1)) * 16));
}

// ---------------------------------------------------------------------------
// bf16x3 HMMA GEMM: C[M,N] = act(A @ W + bias)
// A split (Ah,Al) [M,K] row-major; W split transposed [N,K].
// CTA tile 128x128, 8 warps (warp tile 32x64), K-chunk 32, K % 32 == 0,
// N % 128 == 0. grid = (N/128, ceil(M/128)).
// ---------------------------------------------------------------------------
template<int ACT>
__global__ __launch_bounds__(256, 2)
void mma_gemm_kernel(const __nv_bfloat16* __restrict__ Ah,
                     const __nv_bfloat16* __restrict__ Al,
                     const __nv_bfloat16* __restrict__ Bh,   // [N,K]
                     const __nv_bfloat16* __restrict__ Bl,
                     const float* __restrict__ bias,
                     float* __restrict__ C, int ldc,
                     int M, int K, int N)
{
    __shared__ __align__(16) char sm[32768];  // AH | AL | BH | BL, 8KB each
    const uint32_t sb = smem_u32(sm);
    const uint32_t oAH = 0, oAL = 8192, oBH = 16384, oBL = 24576;

    int tid = threadIdx.x;
    int wid = tid >> 5;
    int lane = tid & 31;
    int wm = wid & 3;              // warp M index (0..3) -> 32 rows each
    int wn = wid >> 2;             // warp N index (0..1) -> 64 cols each
    int row0 = blockIdx.y * 128;
    int col0 = blockIdx.x * 128;

    float acc[2][8][4];
    #pragma unroll
    for (int i = 0; i < 2; i++)
        #pragma unroll
        for (int j = 0; j < 8; j++)
            #pragma unroll
            for (int q = 0; q < 4; q++) acc[i][j][q] = 0.f;

    // ldmatrix lane address components
    int Lg = lane >> 3;            // group 0..3
    int Lr = lane & 7;             // row within group

    const int nchunks = K >> 5;
    for (int ch = 0; ch < nchunks; ch++) {
        int k0 = ch << 5;
        // ---- global -> smem (A: 128x32 halfs, guarded; B: 128x32) ----
        #pragma unroll
        for (int it = 0; it < 2; it++) {
            int idx = tid + it * 256;        // 0..511
            int r = idx >> 2, ci = idx & 3;
            uint32_t sw = swa(r, ci);
            int gr = row0 + r;
            uint4 vh = make_uint4(0u, 0u, 0u, 0u), vl = vh;
            if (gr < M) {
                size_t o = (size_t)gr * K + k0 + ci * 8;
                vh = *(const uint4*)(Ah + o);
                vl = *(const uint4*)(Al + o);
            }
            *(uint4*)(sm + oAH + sw) = vh;
            *(uint4*)(sm + oAL + sw) = vl;
        }
        #pragma unroll
        for (int it = 0; it < 2; it++) {
            int idx = tid + it * 256;
            int r = idx >> 2, ci = idx & 3;
            uint32_t sw = swa(r, ci);
            size_t o = (size_t)(col0 + r) * K + k0 + ci * 8;
            *(uint4*)(sm + oBH + sw) = *(const uint4*)(Bh + o);
            *(uint4*)(sm + oBL + sw) = *(const uint4*)(Bl + o);
        }
        __syncthreads();

        // ---- compute: 2 k-steps of 16 ----
        #pragma unroll
        for (int ks = 0; ks < 2; ks++) {
            uint32_t ah[2][4], al[2][4];
            #pragma unroll
            for (int ma = 0; ma < 2; ma++) {
                int ar = wm * 32 + ma * 16 + Lr + (Lg & 1) * 8;
                int ac = ks * 2 + (Lg >> 1);
                uint32_t sw = swa(ar, ac);
                ldsm4(ah[ma][0], ah[ma][1], ah[ma][2], ah[ma][3], sb + oAH + sw);
                ldsm4(al[ma][0], al[ma][1], al[ma][2], al[ma][3], sb + oAL + sw);
            }
            #pragma unroll
            for (int g = 0; g < 4; g++) {    // 4 n16-groups = 8 n-atoms
                int br = wn * 64 + g * 16 + Lr + (Lg >> 1) * 8;
                int bc = ks * 2 + (Lg & 1);
                uint32_t sw = swa(br, bc);
                uint32_t bh[4], bl[4];
                ldsm4(bh[0], bh[1], bh[2], bh[3], sb + oBH + sw);
                ldsm4(bl[0], bl[1], bl[2], bl[3], sb + oBL + sw);
                #pragma unroll
                for (int ma = 0; ma < 2; ma++) {
                    mma16816(acc[ma][g*2+0], ah[ma], bh + 0);
                    mma16816(acc[ma][g*2+1], ah[ma], bh + 2);
                    mma16816(acc[ma][g*2+0], ah[ma], bl + 0);
                    mma16816(acc[ma][g*2+1], ah[ma], bl + 2);
                    mma16816(acc[ma][g*2+0], al[ma], bh + 0);
                    mma16816(acc[ma][g*2+1], al[ma], bh + 2);
                }
            }
        }
        __syncthreads();
    }

    // ---- epilogue: fragment -> global with bias + leaky_relu ----
    int rbase = row0 + wm * 32 + (lane >> 2);
    int cbase = col0 + wn * 64 + (lane & 3) * 2;
    #pragma unroll
    for (int ma = 0; ma < 2; ma++) {
        #pragma unroll
        for (int na = 0; na < 8; na++) {
            int gc = cbase + na * 8;
            float b0 = bias ? bias[gc] : 0.f;
            float b1 = bias ? bias[gc + 1] : 0.f;
            #pragma unroll
            for (int h = 0; h < 2; h++) {       // c0/c1 then c2/c3 (row +8)
                int gr = rbase + ma * 16 + h * 8;
                if (gr < M) {
                    float v0 = acc[ma][na][h * 2 + 0] + b0;
                    float v1 = acc[ma][na][h * 2 + 1] + b1;
                    if (ACT == 1) {
                        v0 = v0 > 0.f ? v0 : SLOPE * v0;
                        v1 = v1 > 0.f ? v1 : SLOPE * v1;
                    }
                    float2 v = make_float2(v0, v1);
                    *(float2*)(C + (size_t)gr * ldc + gc) = v;
                }
            }
        }
    }
}

// ---------------------------------------------------------------------------
// fp32 -> bf16 hi/lo split (elementwise; and transposed variant for weights)
// ---------------------------------------------------------------------------
__global__ void splitA_kernel(const float* __restrict__ X,
                              __nv_bfloat16* __restrict__ H,
                              __nv_bfloat16* __restrict__ L, long n)
{
    long i = (long)blockIdx.x * blockDim.x + threadIdx.x;
    if (i >= n) return;
    float a = X[i];
    __nv_bfloat16 h = __float2bfloat16(a);
    H[i] = h;
    L[i] = __float2bfloat16(a - __bfloat162float(h));
}

__global__ void splitWT_kernel(const float* __restrict__ W,   // [K,N]
                               __nv_bfloat16* __restrict__ H, // [N,K]
                               __nv_bfloat16* __restrict__ L,
                               int K, int N)
{
    long i = (long)blockIdx.x * blockDim.x + threadIdx.x;
    if (i >= (long)K * N) return;
    int k = (int)(i / N), nn = (int)(i % N);
    float a = W[i];
    __nv_bfloat16 h = __float2bfloat16(a);
    long o = (long)nn * K + k;
    H[o] = h;
    L[o] = __float2bfloat16(a - __bfloat162float(h));
}

// ---------------------------------------------------------------------------
// Edge dtype probe + graph preprocessing
// ---------------------------------------------------------------------------
__global__ void probe_kernel(const int* __restrict__ ei32, int nwords)
{
    __shared__ int nz;
    if (threadIdx.x == 0) nz = 0;
    __syncthreads();
    int lim = nwords < 4096 ? nwords : 4096;
    for (int i = 1 + 2 * threadIdx.x; i < lim; i += 2 * blockDim.x)
        if (ei32[i] != 0) atomicAdd(&nz, 1);
    __syncthreads();
    if (threadIdx.x == 0) g_is64 = (nz == 0) ? 1 : 0;
}

__device__ __forceinline__ int edge_at(const void* base, long i, int is64)
{
    return is64 ? (int)((const long long*)base)[i] : ((const int*)base)[i];
}

__global__ void zero_cnt_kernel(int n) {
    int i = blockIdx.x * blockDim.x + threadIdx.x;
    if (i < n) g_cnt[i] = 0;
}

__global__ void count_kernel(const void* __restrict__ ei, int e, int n) {
    int i = blockIdx.x * blockDim.x + threadIdx.x;
    if (i >= e) return;
    int is64 = g_is64;
    int d = edge_at(ei, (long)e + i, is64);
    if ((unsigned)d < (unsigned)n) atomicAdd(&g_cnt[d], 1);
}

__global__ void dinv_kernel(int n) {
    int i = blockIdx.x * blockDim.x + threadIdx.x;
    if (i < n) g_dinv[i] = rsqrtf((float)(g_cnt[i] + 1));
}

__global__ void scan_kernel(int n) {
    __shared__ int sh[1024];
    __shared__ int carry_sh;
    int tid = threadIdx.x;
    if (tid == 0) carry_sh = 0;
    __syncthreads();
    for (int base = 0; base < n; base += 1024) {
        int v = (base + tid < n) ? g_cnt[base + tid] : 0;
        sh[tid] = v;
        __syncthreads();
        for (int off = 1; off < 1024; off <<= 1) {
            int t = (tid >= off) ? sh[tid - off] : 0;
            __syncthreads();
            sh[tid] += t;
            __syncthreads();
        }
        int carry = carry_sh;
        if (base + tid < n) {
            int ex = carry + sh[tid] - v;
            g_rowptr[base + tid] = ex;
            g_cursor[base + tid] = ex;
        }
        __syncthreads();
        if (tid == 0) carry_sh = carry + sh[1023];
        __syncthreads();
    }
    if (threadIdx.x == 0) g_rowptr[n] = carry_sh;
}

__global__ void fill_kernel(const void* __restrict__ ei, int e, int n) {
    int i = blockIdx.x * blockDim.x + threadIdx.x;
    if (i >= e) return;
    int is64 = g_is64;
    int s = edge_at(ei, i, is64);
    int d = edge_at(ei, (long)e + i, is64);
    if ((unsigned)d < (unsigned)n && (unsigned)s < (unsigned)n) {
        int pos = atomicAdd(&g_cursor[d], 1);
        if (pos < EE) g_colsrc[pos] = s;
    }
}

// ---------------------------------------------------------------------------
// SIMT SGEMM (kept for small-K continuous embedding layers, K=13)
// ---------------------------------------------------------------------------
template<int ACT>
__global__ __launch_bounds__(256)
void sgemm_kernel(const float* __restrict__ A, int lda,
                  const float* __restrict__ W,
                  const float* __restrict__ bias,
                  float* __restrict__ C, int ldc,
                  int M, int K, int NC)
{
    const int BM = 128, BN = 128, BK = 8;
    __shared__ float As[BK][BM];
    __shared__ float Ws[BK][BN];

    int tid = threadIdx.x;
    int tx = tid & 15;
    int ty = tid >> 4;
    int row0 = blockIdx.y * BM;
    int col0 = blockIdx.x * BN;

    float acc[8][8];
    #pragma unroll
    for (int i = 0; i < 8; i++)
        #pragma unroll
        for (int j = 0; j < 8; j++) acc[i][j] = 0.f;

    int a_row = tid >> 1;
    int a_col = (tid & 1) * 4;
    int w_k = tid >> 5;
    int w_n = (tid & 31) * 4;

    for (int k0 = 0; k0 < K; k0 += BK) {
        #pragma unroll
        for (int j = 0; j < 4; j++) {
            int r = row0 + a_row, c = k0 + a_col + j;
            As[a_col + j][a_row] = (r < M && c < K) ? A[(long)r * lda + c] : 0.f;
        }
        #pragma unroll
        for (int j = 0; j < 4; j++) {
            int kk = k0 + w_k, nn = col0 + w_n + j;
            Ws[w_k][w_n + j] = (kk < K && nn < NC) ? W[(long)kk * NC + nn] : 0.f;
        }
        __syncthreads();
        #pragma unroll
        for (int k = 0; k < BK; k++) {
            float a[8], b[8];
            #pragma unroll
            for (int i = 0; i < 8; i++) a[i] = As[k][ty * 8 + i];
            #pragma unroll
            for (int j = 0; j < 8; j++) b[j] = Ws[k][tx * 8 + j];
            #pragma unroll
            for (int i = 0; i < 8; i++)
                #pragma unroll
                for (int j = 0; j < 8; j++)
                    acc[i][j] += a[i] * b[j];
        }
        __syncthreads();
    }

    #pragma unroll
    for (int i = 0; i < 8; i++) {
        int r = row0 + ty * 8 + i;
        if (r >= M) continue;
        #pragma unroll
        for (int j = 0; j < 8; j++) {
            int c = col0 + tx * 8 + j;
            if (c >= NC) continue;
            float v = acc[i][j];
            if (bias) v += bias[c];
            if (ACT == 1) v = v > 0.f ? v : SLOPE * v;
            C[(long)r * ldc + c] = v;
        }
    }
}

// ---------------------------------------------------------------------------
// GCN aggregation (one warp per node)
// ---------------------------------------------------------------------------
__global__ __launch_bounds__(256)
void agg_kernel(const float* __restrict__ Y, const float* __restrict__ bias,
                float* __restrict__ out, int ldc, int n)
{
    int warp = (blockIdx.x * blockDim.x + threadIdx.x) >> 5;
    int lane = threadIdx.x & 31;
    if (warp >= n) return;
    int beg = g_rowptr[warp], end = g_rowptr[warp + 1];
    float acc[8];
    #pragma unroll
    for (int j = 0; j < 8; j++) acc[j] = 0.f;
    for (int e = beg; e < end; e++) {
        int s = g_colsrc[e];
        float w = g_dinv[s];
        const float* yr = Y + (long)s * EMB;
        #pragma unroll
        for (int j = 0; j < 8; j++)
            acc[j] += yr[lane + 32 * j] * w;
    }
    float di = g_dinv[warp];
    const float* ys = Y + (long)warp * EMB;
    #pragma unroll
    for (int j = 0; j < 8; j++) {
        int c = lane + 32 * j;
        float v = di * acc[j] + di * di * ys[c] + bias[c];
        v = v > 0.f ? v : SLOPE * v;
        out[(long)warp * ldc + c] = v;
    }
}

// ---------------------------------------------------------------------------
// Final sigmoid head + output assembly
// ---------------------------------------------------------------------------
__global__ __launch_bounds__(256)
void final_kernel(const float* __restrict__ Wl2, const float* __restrict__ bl2, int n)
{
    int warp = (blockIdx.x * blockDim.x + threadIdx.x) >> 5;
    int lane = threadIdx.x & 31;
    if (warp >= n) return;
    const float* sr = g_S + (long)warp * EMB;
    float a = 0.f;
    #pragma unroll
    for (int j = 0; j < 8; j++) {
        int c = lane + 32 * j;
        a += sr[c] * Wl2[c];
    }
    #pragma unroll
    for (int off = 16; off > 0; off >>= 1)
        a += __shfl_xor_sync(0xffffffffu, a, off);
    if (lane == 0)
        g_sci[warp] = 1.f / (1.f + expf(-(a + bl2[0])));
}

__global__ void writeout_kernel(float* __restrict__ out, int n)
{
    long idx = (long)blockIdx.x * blockDim.x + threadIdx.x;
    long tot = (long)n * HID;
    if (idx < tot) {
        float v = g_H[idx];
        out[3L * n + idx] = v;
        out[3L * n + tot + idx] = v;
    }
    if (idx < n) {
        float v = g_sci[idx];
        out[idx] = v;
        out[(long)n + idx] = v;
        out[2L * n + idx] = v;
    }
}

// ---------------------------------------------------------------------------
// Launch
// ---------------------------------------------------------------------------
extern "C" void kernel_launch(void* const* d_in, const int* in_sizes, int n_in,
                              void* d_out, int out_size)
{
    const float* discrete_x = (const float*)d_in[0];
    const float* continous_x = (const float*)d_in[1];
    const float* Wd  = (const float*)d_in[2];
    const float* bd  = (const float*)d_in[3];
    const float* Wc1 = (const float*)d_in[4];
    const float* bc1 = (const float*)d_in[5];
    const float* Wc2 = (const float*)d_in[6];
    const float* bc2 = (const float*)d_in[7];
    const float* Wg0 = (const float*)d_in[8];
    const float* bg0 = (const float*)d_in[9];
    const float* Wg1 = (const float*)d_in[10];
    const float* bg1 = (const float*)d_in[11];
    const float* Wg2 = (const float*)d_in[12];
    const float* bg2 = (const float*)d_in[13];
    const float* Wf  = (const float*)d_in[14];
    const float* bf  = (const float*)d_in[15];
    const float* Wl1 = (const float*)d_in[16];
    const float* bl1 = (const float*)d_in[17];
    const float* Wl2 = (const float*)d_in[18];
    const float* bl2 = (const float*)d_in[19];
    const void*  edge_index = d_in[20];

    const int n = in_sizes[0] / DDISC;       // 50000
    const int e = in_sizes[20] / 2;          // 800000

    float *pX4, *pG0, *pG1, *pY, *pH, *pS;
    cudaGetSymbolAddress((void**)&pX4, g_X4);
    cudaGetSymbolAddress((void**)&pG0, g_G0);
    cudaGetSymbolAddress((void**)&pG1, g_G1);
    cudaGetSymbolAddress((void**)&pY,  g_Y);
    cudaGetSymbolAddress((void**)&pH,  g_H);
    cudaGetSymbolAddress((void**)&pS,  g_S);
    __nv_bfloat16 *pAh, *pAl, *pGh, *pGl, *pHh, *pHl, *pDh, *pDl, *pWth, *pWtl;
    cudaGetSymbolAddress((void**)&pAh, g_Ah);
    cudaGetSymbolAddress((void**)&pAl, g_Al);
    cudaGetSymbolAddress((void**)&pGh, g_Gh);
    cudaGetSymbolAddress((void**)&pGl, g_Gl);
    cudaGetSymbolAddress((void**)&pHh, g_Hh);
    cudaGetSymbolAddress((void**)&pHl, g_Hl);
    cudaGetSymbolAddress((void**)&pDh, g_Dh);
    cudaGetSymbolAddress((void**)&pDl, g_Dl);
    cudaGetSymbolAddress((void**)&pWth, g_Wth);
    cudaGetSymbolAddress((void**)&pWtl, g_Wtl);

    dim3 blk(256);
    const int mtiles = (n + 127) / 128;   // 391

    // ---- graph preprocessing ----
    probe_kernel<<<1, 256>>>((const int*)edge_index, 2 * e);
    zero_cnt_kernel<<<(n + 255) / 256, blk>>>(n);
    count_kernel<<<(e + 255) / 256, blk>>>(edge_index, e, n);
    dinv_kernel<<<(n + 255) / 256, blk>>>(n);
    scan_kernel<<<1, 1024>>>(n);
    fill_kernel<<<(e + 255) / 256, blk>>>(edge_index, e, n);

    // ---- discrete embeddings via HMMA (K=64) ----
    {
        long nd = (long)n * DDISC;
        splitA_kernel<<<(unsigned)((nd + 255) / 256), blk>>>(discrete_x, pDh, pDl, nd);
        splitWT_kernel<<<(DDISC * EMB + 255) / 256, blk>>>(Wd, pWth, pWtl, DDISC, EMB);
        mma_gemm_kernel<1><<<dim3(2, mtiles), blk>>>(pDh, pDl, pWth, pWtl,
                                                     bd, pX4 + 0, CAT, n, DDISC, EMB);
        splitWT_kernel<<<(DDISC * EMB + 255) / 256, blk>>>(Wg0, pWth, pWtl, DDISC, EMB);
        mma_gemm_kernel<1><<<dim3(2, mtiles), blk>>>(pDh, pDl, pWth, pWtl,
                                                     bg0, pG0, EMB, n, DDISC, EMB);
    }

    // ---- continuous embeddings (SIMT, K=13) ----
    {
        dim3 grid((EMB + 127) / 128, mtiles);
        sgemm_kernel<1><<<grid, blk>>>(continous_x,         3*DCONT, Wc1, bc1, pX4 + EMB,   CAT, n, DCONT, EMB);
        sgemm_kernel<1><<<grid, blk>>>(continous_x + DCONT, 3*DCONT, Wc2, bc2, pX4 + 2*EMB, CAT, n, DCONT, EMB);
    }

    // ---- GCN conv 1 ----
    {
        long ne = (long)n * EMB;
        splitA_kernel<<<(unsigned)((ne + 255) / 256), blk>>>(pG0, pGh, pGl, ne);
        splitWT_kernel<<<(EMB * EMB + 255) / 256, blk>>>(Wg1, pWth, pWtl, EMB, EMB);
        mma_gemm_kernel<0><<<dim3(2, mtiles), blk>>>(pGh, pGl, pWth, pWtl,
                                                     (const float*)nullptr, pY, EMB, n, EMB, EMB);
        agg_kernel<<<(n * 32 + 255) / 256, blk>>>(pY, bg1, pG1, EMB, n);

        // ---- GCN conv 2 ----
        splitA_kernel<<<(unsigned)((ne + 255) / 256), blk>>>(pG1, pGh, pGl, ne);
        splitWT_kernel<<<(EMB * EMB + 255) / 256, blk>>>(Wg2, pWth, pWtl, EMB, EMB);
        mma_gemm_kernel<0><<<dim3(2, mtiles), blk>>>(pGh, pGl, pWth, pWtl,
                                                     (const float*)nullptr, pY, EMB, n, EMB, EMB);
        agg_kernel<<<(n * 32 + 255) / 256, blk>>>(pY, bg2, pX4 + 3*EMB, CAT, n);
    }

    // ---- fusion MLP ----
    {
        long nc = (long)n * CAT;
        splitA_kernel<<<(unsigned)((nc + 255) / 256), blk>>>(pX4, pAh, pAl, nc);
        splitWT_kernel<<<(CAT * HID + 255) / 256, blk>>>(Wf, pWth, pWtl, CAT, HID);
        mma_gemm_kernel<1><<<dim3(4, mtiles), blk>>>(pAh, pAl, pWth, pWtl,
                                                     bf, pH, HID, n, CAT, HID);
        long nh = (long)n * HID;
        splitA_kernel<<<(unsigned)((nh + 255) / 256), blk>>>(pH, pHh, pHl, nh);
        splitWT_kernel<<<(HID * EMB + 255) / 256, blk>>>(Wl1, pWth, pWtl, HID, EMB);
        mma_gemm_kernel<1><<<dim3(2, mtiles), blk>>>(pHh, pHl, pWth, pWtl,
                                                     bl1, pS, EMB, n, HID, EMB);
    }

    // ---- final sigmoid head ----
    final_kernel<<<(n * 32 + 255) / 256, blk>>>(Wl2, bl2, n);

    // ---- assemble output tuple ----
    {
        long tot = (long)n * HID;
        writeout_kernel<<<(unsigned)((tot + 255) / 256), blk>>>((float*)d_out, n);
    }
}

// round 5
// speedup vs baseline: 3.2957x; 1.3810x over previous
#include <cuda_runtime.h>
#include <cuda_bf16.h>
#include <math.h>
#include <stdint.h>

// ---------------------------------------------------------------------------
// Problem constants
// ---------------------------------------------------------------------------
#define NN    50000
#define EE    800000
#define EMB   256
#define HID   512
#define DDISC 64
#define DCONT 13
#define CAT   (4*EMB)      // 1024
#define SLOPE 0.01f

// ---------------------------------------------------------------------------
// Scratch — __device__ globals (no cudaMalloc allowed)
// ---------------------------------------------------------------------------
__device__ float g_Y [(long)NN*EMB];     // conv pre-aggregation (fp32)
__device__ float g_S [(long)NN*EMB];     // s
__device__ float g_sci[NN];
__device__ float g_dinv[NN];
__device__ int   g_cnt[NN];
__device__ int   g_rowptr[NN+1];
__device__ int   g_cursor[NN];
__device__ int   g_colsrc[EE];
__device__ int   g_is64;

// bf16 split buffers (hi/lo)
__device__ __align__(16) __nv_bfloat16 g_Ah[(long)NN*CAT];   // concat split
__device__ __align__(16) __nv_bfloat16 g_Al[(long)NN*CAT];
__device__ __align__(16) __nv_bfloat16 g_Gh[(long)NN*EMB];   // gcn activation split
__device__ __align__(16) __nv_bfloat16 g_Gl[(long)NN*EMB];
__device__ __align__(16) __nv_bfloat16 g_Hh[(long)NN*HID];   // h_ci split
__device__ __align__(16) __nv_bfloat16 g_Hl[(long)NN*HID];
__device__ __align__(16) __nv_bfloat16 g_Dh[(long)NN*DDISC]; // discrete_x split
__device__ __align__(16) __nv_bfloat16 g_Dl[(long)NN*DDISC];
__device__ __align__(16) __nv_bfloat16 g_Wth[(long)CAT*HID]; // transposed weight split
__device__ __align__(16) __nv_bfloat16 g_Wtl[(long)CAT*HID];

// ---------------------------------------------------------------------------
// asm helpers (base ISA only — must compile for compute_103)
// ---------------------------------------------------------------------------
__device__ __forceinline__ uint32_t smem_u32(const void* p) {
    uint32_t a;
    asm("{ .reg .u64 t; cvta.to.shared.u64 t, %1; cvt.u32.u64 %0, t; }" : "=r"(a) : "l"(p));
    return a;
}
__device__ __forceinline__ void ldsm4(uint32_t& r0, uint32_t& r1, uint32_t& r2, uint32_t& r3,
                                      uint32_t addr) {
    asm volatile("ldmatrix.sync.aligned.m8n8.x4.shared.b16 {%0,%1,%2,%3}, [%4];"
                 : "=r"(r0), "=r"(r1), "=r"(r2), "=r"(r3) : "r"(addr));
}
__device__ __forceinline__ void mma16816(float* c, const uint32_t* a, const uint32_t* b) {
    asm volatile(
        "mma.sync.aligned.m16n8k16.row.col.f32.bf16.bf16.f32 "
        "{%0,%1,%2,%3}, {%4,%5,%6,%7}, {%8,%9}, {%0,%1,%2,%3};"
        : "+f"(c[0]), "+f"(c[1]), "+f"(c[2]), "+f"(c[3])
        : "r"(a[0]), "r"(a[1]), "r"(a[2]), "r"(a[3]), "r"(b[0]), "r"(b[1]));
}
__device__ __forceinline__ void cp16(uint32_t dst, const void* src, int sz) {
    asm volatile("cp.async.cg.shared.global [%0], [%1], 16, %2;"
                 :: "r"(dst), "l"(src), "r"(sz) : "memory");
}
__device__ __forceinline__ void cp_commit() {
    asm volatile("cp.async.commit_group;" ::: "memory");
}
__device__ __forceinline__ void cp_wait1() {
    asm volatile("cp.async.wait_group 1;" ::: "memory");
}
__device__ __forceinline__ void cp_wait0() {
    asm volatile("cp.async.wait_group 0;" ::: "memory");
}
// byte offset inside a [rows][32 halfs] tile (row stride 64B, 16B-chunk swizzle)
__device__ __forceinline__ uint32_t swa(int r, int ci) {
    return (uint32_t)(r * 64 + ((ci ^ (r & 3) ^ ((r >> 2) & 1)) * 16));
}
__device__ __forceinline__ void split_store(__nv_bfloat16* H, __nv_bfloat16* L,
                                            size_t off, float v0, float v1) {
    __nv_bfloat16 h0 = __float2bfloat16(v0);
    __nv_bfloat16 h1 = __float2bfloat16(v1);
    __nv_bfloat16 l0 = __float2bfloat16(v0 - __bfloat162float(h0));
    __nv_bfloat16 l1 = __float2bfloat16(v1 - __bfloat162float(h1));
    *(__nv_bfloat162*)(H + off) = __nv_bfloat162(h0, h1);
    *(__nv_bfloat162*)(L + off) = __nv_bfloat162(l0, l1);
}

// ---------------------------------------------------------------------------
// bf16x3 HMMA GEMM, cp.async double-buffered.
// C = act(A @ W + bias). A split [M,K] row-major; W split transposed [N,K].
// CTA tile 128x128, 8 warps (warp tile 32x64), K-chunk 32, K%32==0, N%128==0.
// MODE 0: write Cf fp32.  MODE 1: write split (Ch,Cl).
// MODE 2: write split + fp32 into Cf AND Cf2 (dual copy for output tuple).
// Dynamic smem: 2 stages x 32KB = 64KB.
// ---------------------------------------------------------------------------
#define STG 32768
template<int ACT, int MODE>
__global__ __launch_bounds__(256, 2)
void mma_gemm_kernel(const __nv_bfloat16* __restrict__ Ah,
                     const __nv_bfloat16* __restrict__ Al,
                     const __nv_bfloat16* __restrict__ Bh,   // [N,K]
                     const __nv_bfloat16* __restrict__ Bl,
                     const float* __restrict__ bias,
                     float* __restrict__ Cf, float* __restrict__ Cf2, int ldf,
                     __nv_bfloat16* __restrict__ Ch, __nv_bfloat16* __restrict__ Cl, int lds,
                     int M, int K, int N)
{
    extern __shared__ char sm[];
    const uint32_t sb = smem_u32(sm);
    const uint32_t oAH = 0, oAL = 8192, oBH = 16384, oBL = 24576;

    int tid = threadIdx.x;
    int wid = tid >> 5;
    int lane = tid & 31;
    int wm = wid & 3;
    int wn = wid >> 2;
    int row0 = blockIdx.y * 128;
    int col0 = blockIdx.x * 128;

    float acc[2][8][4];
    #pragma unroll
    for (int i = 0; i < 2; i++)
        #pragma unroll
        for (int j = 0; j < 8; j++)
            #pragma unroll
            for (int q = 0; q < 4; q++) acc[i][j][q] = 0.f;

    int Lg = lane >> 3;
    int Lr = lane & 7;
    const int nchunks = K >> 5;

    // ---- cp.async prefetch of one K-chunk into a stage buffer ----
    auto prefetch = [&](int ch, int stage) {
        int k0 = ch << 5;
        uint32_t base = sb + stage * STG;
        #pragma unroll
        for (int it = 0; it < 2; it++) {
            int idx = tid + it * 256;          // 0..511
            int r = idx >> 2, ci = idx & 3;
            uint32_t sw = swa(r, ci);
            int gr = row0 + r;
            int ok = (gr < M) ? 16 : 0;
            size_t ga = (size_t)(ok ? gr : 0) * K + k0 + ci * 8;
            cp16(base + oAH + sw, Ah + ga, ok);
            cp16(base + oAL + sw, Al + ga, ok);
            size_t gb = (size_t)(col0 + r) * K + k0 + ci * 8;
            cp16(base + oBH + sw, Bh + gb, 16);
            cp16(base + oBL + sw, Bl + gb, 16);
        }
        cp_commit();
    };

    prefetch(0, 0);
    for (int ch = 0; ch < nchunks; ch++) {
        if (ch + 1 < nchunks) {
            prefetch(ch + 1, (ch + 1) & 1);
            cp_wait1();
        } else {
            cp_wait0();
        }
        __syncthreads();
        uint32_t base = sb + (ch & 1) * STG;

        #pragma unroll
        for (int ks = 0; ks < 2; ks++) {
            uint32_t ah[2][4], al[2][4];
            #pragma unroll
            for (int ma = 0; ma < 2; ma++) {
                int ar = wm * 32 + ma * 16 + Lr + (Lg & 1) * 8;
                int ac = ks * 2 + (Lg >> 1);
                uint32_t sw = swa(ar, ac);
                ldsm4(ah[ma][0], ah[ma][1], ah[ma][2], ah[ma][3], base + oAH + sw);
                ldsm4(al[ma][0], al[ma][1], al[ma][2], al[ma][3], base + oAL + sw);
            }
            #pragma unroll
            for (int g = 0; g < 4; g++) {
                int br = wn * 64 + g * 16 + Lr + (Lg >> 1) * 8;
                int bc = ks * 2 + (Lg & 1);
                uint32_t sw = swa(br, bc);
                uint32_t bh[4], bl[4];
                ldsm4(bh[0], bh[1], bh[2], bh[3], base + oBH + sw);
                ldsm4(bl[0], bl[1], bl[2], bl[3], base + oBL + sw);
                #pragma unroll
                for (int ma = 0; ma < 2; ma++) {
                    mma16816(acc[ma][g*2+0], ah[ma], bh + 0);
                    mma16816(acc[ma][g*2+1], ah[ma], bh + 2);
                    mma16816(acc[ma][g*2+0], ah[ma], bl + 0);
                    mma16816(acc[ma][g*2+1], ah[ma], bl + 2);
                    mma16816(acc[ma][g*2+0], al[ma], bh + 0);
                    mma16816(acc[ma][g*2+1], al[ma], bh + 2);
                }
            }
        }
        __syncthreads();
    }

    // ---- epilogue ----
    int rbase = row0 + wm * 32 + (lane >> 2);
    int cbase = col0 + wn * 64 + (lane & 3) * 2;
    #pragma unroll
    for (int ma = 0; ma < 2; ma++) {
        #pragma unroll
        for (int na = 0; na < 8; na++) {
            int gc = cbase + na * 8;
            float b0 = bias ? bias[gc] : 0.f;
            float b1 = bias ? bias[gc + 1] : 0.f;
            #pragma unroll
            for (int h = 0; h < 2; h++) {
                int gr = rbase + ma * 16 + h * 8;
                if (gr < M) {
                    float v0 = acc[ma][na][h * 2 + 0] + b0;
                    float v1 = acc[ma][na][h * 2 + 1] + b1;
                    if (ACT == 1) {
                        v0 = v0 > 0.f ? v0 : SLOPE * v0;
                        v1 = v1 > 0.f ? v1 : SLOPE * v1;
                    }
                    if (MODE == 0 || MODE == 2) {
                        *(float2*)(Cf + (size_t)gr * ldf + gc) = make_float2(v0, v1);
                        if (MODE == 2)
                            *(float2*)(Cf2 + (size_t)gr * ldf + gc) = make_float2(v0, v1);
                    }
                    if (MODE == 1 || MODE == 2)
                        split_store(Ch, Cl, (size_t)gr * lds + gc, v0, v1);
                }
            }
        }
    }
}

// ---------------------------------------------------------------------------
// fp32 -> bf16 hi/lo split (input features; and transposed variant for weights)
// ---------------------------------------------------------------------------
__global__ void splitA_kernel(const float* __restrict__ X,
                              __nv_bfloat16* __restrict__ H,
                              __nv_bfloat16* __restrict__ L, long n)
{
    long i = (long)blockIdx.x * blockDim.x + threadIdx.x;
    if (i >= n) return;
    float a = X[i];
    __nv_bfloat16 h = __float2bfloat16(a);
    H[i] = h;
    L[i] = __float2bfloat16(a - __bfloat162float(h));
}

__global__ void splitWT_kernel(const float* __restrict__ W,   // [K,N]
                               __nv_bfloat16* __restrict__ H, // [N,K]
                               __nv_bfloat16* __restrict__ L,
                               int K, int N)
{
    long i = (long)blockIdx.x * blockDim.x + threadIdx.x;
    if (i >= (long)K * N) return;
    int k = (int)(i / N), nn = (int)(i % N);
    float a = W[i];
    __nv_bfloat16 h = __float2bfloat16(a);
    long o = (long)nn * K + k;
    H[o] = h;
    L[o] = __float2bfloat16(a - __bfloat162float(h));
}

// ---------------------------------------------------------------------------
// Edge dtype probe + graph preprocessing
// ---------------------------------------------------------------------------
__global__ void probe_kernel(const int* __restrict__ ei32, int nwords)
{
    __shared__ int nz;
    if (threadIdx.x == 0) nz = 0;
    __syncthreads();
    int lim = nwords < 4096 ? nwords : 4096;
    for (int i = 1 + 2 * threadIdx.x; i < lim; i += 2 * blockDim.x)
        if (ei32[i] != 0) atomicAdd(&nz, 1);
    __syncthreads();
    if (threadIdx.x == 0) g_is64 = (nz == 0) ? 1 : 0;
}

__device__ __forceinline__ int edge_at(const void* base, long i, int is64)
{
    return is64 ? (int)((const long long*)base)[i] : ((const int*)base)[i];
}

__global__ void zero_cnt_kernel(int n) {
    int i = blockIdx.x * blockDim.x + threadIdx.x;
    if (i < n) g_cnt[i] = 0;
}

__global__ void count_kernel(const void* __restrict__ ei, int e, int n) {
    int i = blockIdx.x * blockDim.x + threadIdx.x;
    if (i >= e) return;
    int is64 = g_is64;
    int d = edge_at(ei, (long)e + i, is64);
    if ((unsigned)d < (unsigned)n) atomicAdd(&g_cnt[d], 1);
}

__global__ void dinv_kernel(int n) {
    int i = blockIdx.x * blockDim.x + threadIdx.x;
    if (i < n) g_dinv[i] = rsqrtf((float)(g_cnt[i] + 1));
}

// fast single-block scan: serial per-thread segments + one 1024-wide scan
__global__ void scan_kernel(int n) {
    __shared__ int part[1024];
    int tid = threadIdx.x;
    int per = (n + 1023) >> 10;
    int beg = tid * per;
    int end = beg + per < n ? beg + per : n;
    int s = 0;
    for (int i = beg; i < end; i++) s += g_cnt[i];
    part[tid] = s;
    __syncthreads();
    for (int off = 1; off < 1024; off <<= 1) {
        int t = (tid >= off) ? part[tid - off] : 0;
        __syncthreads();
        part[tid] += t;
        __syncthreads();
    }
    int run = part[tid] - s;       // exclusive prefix of this segment
    for (int i = beg; i < end; i++) {
        int v = g_cnt[i];
        g_rowptr[i] = run;
        g_cursor[i] = run;
        run += v;
    }
    if (tid == 1023) g_rowptr[n] = run;
}

__global__ void fill_kernel(const void* __restrict__ ei, int e, int n) {
    int i = blockIdx.x * blockDim.x + threadIdx.x;
    if (i >= e) return;
    int is64 = g_is64;
    int s = edge_at(ei, i, is64);
    int d = edge_at(ei, (long)e + i, is64);
    if ((unsigned)d < (unsigned)n && (unsigned)s < (unsigned)n) {
        int pos = atomicAdd(&g_cursor[d], 1);
        if (pos < EE) g_colsrc[pos] = s;
    }
}

// ---------------------------------------------------------------------------
// SIMT SGEMM for small-K continuous embeds (K=13), writes bf16 split directly.
// ---------------------------------------------------------------------------
__global__ __launch_bounds__(256)
void sgemm_split_kernel(const float* __restrict__ A, int lda,
                        const float* __restrict__ W,
                        const float* __restrict__ bias,
                        __nv_bfloat16* __restrict__ Ch,
                        __nv_bfloat16* __restrict__ Cl, int ldc,
                        int M, int K, int NC)
{
    const int BM = 128, BN = 128, BK = 8;
    __shared__ float As[BK][BM];
    __shared__ float Ws[BK][BN];

    int tid = threadIdx.x;
    int tx = tid & 15;
    int ty = tid >> 4;
    int row0 = blockIdx.y * BM;
    int col0 = blockIdx.x * BN;

    float acc[8][8];
    #pragma unroll
    for (int i = 0; i < 8; i++)
        #pragma unroll
        for (int j = 0; j < 8; j++) acc[i][j] = 0.f;

    int a_row = tid >> 1;
    int a_col = (tid & 1) * 4;
    int w_k = tid >> 5;
    int w_n = (tid & 31) * 4;

    for (int k0 = 0; k0 < K; k0 += BK) {
        #pragma unroll
        for (int j = 0; j < 4; j++) {
            int r = row0 + a_row, c = k0 + a_col + j;
            As[a_col + j][a_row] = (r < M && c < K) ? A[(long)r * lda + c] : 0.f;
        }
        #pragma unroll
        for (int j = 0; j < 4; j++) {
            int kk = k0 + w_k, nn = col0 + w_n + j;
            Ws[w_k][w_n + j] = (kk < K && nn < NC) ? W[(long)kk * NC + nn] : 0.f;
        }
        __syncthreads();
        #pragma unroll
        for (int k = 0; k < BK; k++) {
            float a[8], b[8];
            #pragma unroll
            for (int i = 0; i < 8; i++) a[i] = As[k][ty * 8 + i];
            #pragma unroll
            for (int j = 0; j < 8; j++) b[j] = Ws[k][tx * 8 + j];
            #pragma unroll
            for (int i = 0; i < 8; i++)
                #pragma unroll
                for (int j = 0; j < 8; j++)
                    acc[i][j] += a[i] * b[j];
        }
        __syncthreads();
    }

    #pragma unroll
    for (int i = 0; i < 8; i++) {
        int r = row0 + ty * 8 + i;
        if (r >= M) continue;
        #pragma unroll
        for (int j = 0; j < 8; j += 2) {
            int c = col0 + tx * 8 + j;
            if (c + 1 >= NC) continue;
            float v0 = acc[i][j] + bias[c];
            float v1 = acc[i][j + 1] + bias[c + 1];
            v0 = v0 > 0.f ? v0 : SLOPE * v0;
            v1 = v1 > 0.f ? v1 : SLOPE * v1;
            split_store(Ch, Cl, (size_t)r * ldc + c, v0, v1);
        }
    }
}

// ---------------------------------------------------------------------------
// GCN aggregation (one warp per node), writes bf16 split directly
// ---------------------------------------------------------------------------
__global__ __launch_bounds__(256)
void agg_kernel(const float* __restrict__ Y, const float* __restrict__ bias,
                __nv_bfloat16* __restrict__ Oh, __nv_bfloat16* __restrict__ Ol,
                int ldc, int n)
{
    int warp = (blockIdx.x * blockDim.x + threadIdx.x) >> 5;
    int lane = threadIdx.x & 31;
    if (warp >= n) return;
    int beg = g_rowptr[warp], end = g_rowptr[warp + 1];
    float acc[8];
    #pragma unroll
    for (int j = 0; j < 8; j++) acc[j] = 0.f;
    for (int e = beg; e < end; e++) {
        int s = g_colsrc[e];
        float w = g_dinv[s];
        const float* yr = Y + (long)s * EMB;
        #pragma unroll
        for (int j = 0; j < 8; j++)
            acc[j] += yr[lane + 32 * j] * w;
    }
    float di = g_dinv[warp];
    const float* ys = Y + (long)warp * EMB;
    #pragma unroll
    for (int j = 0; j < 4; j++) {
        int c = lane * 2 + 64 * j;          // pairs of adjacent columns
        float a0, a1;
        // remap: original per-lane cols were lane+32*jj; recompute directly
        a0 = 0.f; a1 = 0.f;
        (void)a0; (void)a1;
    }
    // store: each lane owns cols lane+32*j — split-write each element (scalar)
    #pragma unroll
    for (int j = 0; j < 8; j++) {
        int c = lane + 32 * j;
        float v = di * acc[j] + di * di * ys[c] + bias[c];
        v = v > 0.f ? v : SLOPE * v;
        __nv_bfloat16 h = __float2bfloat16(v);
        Oh[(size_t)warp * ldc + c] = h;
        Ol[(size_t)warp * ldc + c] = __float2bfloat16(v - __bfloat162float(h));
    }
}

// ---------------------------------------------------------------------------
// Final sigmoid head + small s_ci writeout
// ---------------------------------------------------------------------------
__global__ __launch_bounds__(256)
void final_kernel(const float* __restrict__ Wl2, const float* __restrict__ bl2, int n)
{
    int warp = (blockIdx.x * blockDim.x + threadIdx.x) >> 5;
    int lane = threadIdx.x & 31;
    if (warp >= n) return;
    const float* sr = g_S + (long)warp * EMB;
    float a = 0.f;
    #pragma unroll
    for (int j = 0; j < 8; j++) {
        int c = lane + 32 * j;
        a += sr[c] * Wl2[c];
    }
    #pragma unroll
    for (int off = 16; off > 0; off >>= 1)
        a += __shfl_xor_sync(0xffffffffu, a, off);
    if (lane == 0)
        g_sci[warp] = 1.f / (1.f + expf(-(a + bl2[0])));
}

__global__ void sci_writeout_kernel(float* __restrict__ out, int n)
{
    int i = blockIdx.x * blockDim.x + threadIdx.x;
    if (i < n) {
        float v = g_sci[i];
        out[i] = v;
        out[n + i] = v;
        out[2L * n + i] = v;
    }
}

// ---------------------------------------------------------------------------
// Launch
// ---------------------------------------------------------------------------
extern "C" void kernel_launch(void* const* d_in, const int* in_sizes, int n_in,
                              void* d_out, int out_size)
{
    const float* discrete_x = (const float*)d_in[0];
    const float* continous_x = (const float*)d_in[1];
    const float* Wd  = (const float*)d_in[2];
    const float* bd  = (const float*)d_in[3];
    const float* Wc1 = (const float*)d_in[4];
    const float* bc1 = (const float*)d_in[5];
    const float* Wc2 = (const float*)d_in[6];
    const float* bc2 = (const float*)d_in[7];
    const float* Wg0 = (const float*)d_in[8];
    const float* bg0 = (const float*)d_in[9];
    const float* Wg1 = (const float*)d_in[10];
    const float* bg1 = (const float*)d_in[11];
    const float* Wg2 = (const float*)d_in[12];
    const float* bg2 = (const float*)d_in[13];
    const float* Wf  = (const float*)d_in[14];
    const float* bf  = (const float*)d_in[15];
    const float* Wl1 = (const float*)d_in[16];
    const float* bl1 = (const float*)d_in[17];
    const float* Wl2 = (const float*)d_in[18];
    const float* bl2 = (const float*)d_in[19];
    const void*  edge_index = d_in[20];

    const int n = in_sizes[0] / DDISC;       // 50000
    const int e = in_sizes[20] / 2;          // 800000

    float *pY, *pS;
    cudaGetSymbolAddress((void**)&pY, g_Y);
    cudaGetSymbolAddress((void**)&pS, g_S);
    __nv_bfloat16 *pAh, *pAl, *pGh, *pGl, *pHh, *pHl, *pDh, *pDl, *pWth, *pWtl;
    cudaGetSymbolAddress((void**)&pAh, g_Ah);
    cudaGetSymbolAddress((void**)&pAl, g_Al);
    cudaGetSymbolAddress((void**)&pGh, g_Gh);
    cudaGetSymbolAddress((void**)&pGl, g_Gl);
    cudaGetSymbolAddress((void**)&pHh, g_Hh);
    cudaGetSymbolAddress((void**)&pHl, g_Hl);
    cudaGetSymbolAddress((void**)&pDh, g_Dh);
    cudaGetSymbolAddress((void**)&pDl, g_Dl);
    cudaGetSymbolAddress((void**)&pWth, g_Wth);
    cudaGetSymbolAddress((void**)&pWtl, g_Wtl);

    cudaFuncSetAttribute(mma_gemm_kernel<0,0>, cudaFuncAttributeMaxDynamicSharedMemorySize, 2*STG);
    cudaFuncSetAttribute(mma_gemm_kernel<1,0>, cudaFuncAttributeMaxDynamicSharedMemorySize, 2*STG);
    cudaFuncSetAttribute(mma_gemm_kernel<1,1>, cudaFuncAttributeMaxDynamicSharedMemorySize, 2*STG);
    cudaFuncSetAttribute(mma_gemm_kernel<1,2>, cudaFuncAttributeMaxDynamicSharedMemorySize, 2*STG);

    dim3 blk(256);
    const int mtiles = (n + 127) / 128;   // 391
    float* outf = (float*)d_out;
    long tot = (long)n * HID;

    // ---- graph preprocessing ----
    probe_kernel<<<1, 256>>>((const int*)edge_index, 2 * e);
    zero_cnt_kernel<<<(n + 255) / 256, blk>>>(n);
    count_kernel<<<(e + 255) / 256, blk>>>(edge_index, e, n);
    dinv_kernel<<<(n + 255) / 256, blk>>>(n);
    scan_kernel<<<1, 1024>>>(n);
    fill_kernel<<<(e + 255) / 256, blk>>>(edge_index, e, n);

    // ---- discrete embeddings via HMMA (K=64), split outputs ----
    {
        long nd = (long)n * DDISC;
        splitA_kernel<<<(unsigned)((nd + 255) / 256), blk>>>(discrete_x, pDh, pDl, nd);
        splitWT_kernel<<<(DDISC * EMB + 255) / 256, blk>>>(Wd, pWth, pWtl, DDISC, EMB);
        mma_gemm_kernel<1,1><<<dim3(2, mtiles), blk, 2*STG>>>(
            pDh, pDl, pWth, pWtl, bd,
            (float*)nullptr, (float*)nullptr, 0, pAh, pAl, CAT, n, DDISC, EMB);
        splitWT_kernel<<<(DDISC * EMB + 255) / 256, blk>>>(Wg0, pWth, pWtl, DDISC, EMB);
        mma_gemm_kernel<1,1><<<dim3(2, mtiles), blk, 2*STG>>>(
            pDh, pDl, pWth, pWtl, bg0,
            (float*)nullptr, (float*)nullptr, 0, pGh, pGl, EMB, n, DDISC, EMB);
    }

    // ---- continuous embeddings (SIMT, K=13), split outputs into concat ----
    {
        dim3 grid((EMB + 127) / 128, mtiles);
        sgemm_split_kernel<<<grid, blk>>>(continous_x,         3*DCONT, Wc1, bc1,
                                          pAh + EMB, pAl + EMB, CAT, n, DCONT, EMB);
        sgemm_split_kernel<<<grid, blk>>>(continous_x + DCONT, 3*DCONT, Wc2, bc2,
                                          pAh + 2*EMB, pAl + 2*EMB, CAT, n, DCONT, EMB);
    }

    // ---- GCN conv 1 ----
    {
        splitWT_kernel<<<(EMB * EMB + 255) / 256, blk>>>(Wg1, pWth, pWtl, EMB, EMB);
        mma_gemm_kernel<0,0><<<dim3(2, mtiles), blk, 2*STG>>>(
            pGh, pGl, pWth, pWtl, (const float*)nullptr,
            pY, (float*)nullptr, EMB, (__nv_bfloat16*)nullptr, (__nv_bfloat16*)nullptr, 0,
            n, EMB, EMB);
        agg_kernel<<<(n * 32 + 255) / 256, blk>>>(pY, bg1, pGh, pGl, EMB, n);

        // ---- GCN conv 2 ----
        splitWT_kernel<<<(EMB * EMB + 255) / 256, blk>>>(Wg2, pWth, pWtl, EMB, EMB);
        mma_gemm_kernel<0,0><<<dim3(2, mtiles), blk, 2*STG>>>(
            pGh, pGl, pWth, pWtl, (const float*)nullptr,
            pY, (float*)nullptr, EMB, (__nv_bfloat16*)nullptr, (__nv_bfloat16*)nullptr, 0,
            n, EMB, EMB);
        agg_kernel<<<(n * 32 + 255) / 256, blk>>>(pY, bg2, pAh + 3*EMB, pAl + 3*EMB, CAT, n);
    }

    // ---- fusion MLP: H = lrelu(X4 @ Wf + bf) -> split + dual fp32 into d_out ----
    {
        splitWT_kernel<<<(CAT * HID + 255) / 256, blk>>>(Wf, pWth, pWtl, CAT, HID);
        mma_gemm_kernel<1,2><<<dim3(4, mtiles), blk, 2*STG>>>(
            pAh, pAl, pWth, pWtl, bf,
            outf + 3L * n, outf + 3L * n + tot, HID, pHh, pHl, HID, n, CAT, HID);
        splitWT_kernel<<<(HID * EMB + 255) / 256, blk>>>(Wl1, pWth, pWtl, HID, EMB);
        mma_gemm_kernel<1,0><<<dim3(2, mtiles), blk, 2*STG>>>(
            pHh, pHl, pWth, pWtl, bl1,
            pS, (float*)nullptr, EMB, (__nv_bfloat16*)nullptr, (__nv_bfloat16*)nullptr, 0,
            n, HID, EMB);
    }

    // ---- final sigmoid head + s_ci writeout ----
    final_kernel<<<(n * 32 + 255) / 256, blk>>>(Wl2, bl2, n);
    sci_writeout_kernel<<<(n + 255) / 256, blk>>>(outf, n);
}